// round 2
// baseline (speedup 1.0000x reference)
#include <cuda_runtime.h>

// Swin Transformer block, fp32 baseline.
// B=8, H=W=128, C=192, NH=6, hd=32, WS=8 (N=64 tokens/window), shift=4, DFF=768.
// Kernel 1: per-window fused [shift+partition -> QKV -> attn(+rpb+mask) -> softmax
//           -> AV -> proj -> +residual -> LN1] writing x1 scratch.
// Kernel 2: row-block fused [x1 @ W1 -> gelu -> @ W2 -> +x1 -> LN2] -> out.

#define CC     192
#define LL     16384
#define BB     8
#define NHEAD  6
#define HD     32
#define WSZ    8
#define NTOK   64
#define SSH    4
#define DFF    768
#define EPS_LN 1e-7f
#define KT_LD  65          // padded row stride for transposed K (bank-conflict free reads)

// scratch: x1 = LN1(shortcut + attn_out)   (~100.7 MB)
__device__ float g_x1[(size_t)BB * LL * CC];

__device__ __forceinline__ int region_label(int p) {
    // shifted-frame region slices: [0,120) [120,124) [124,128)
    return p < (128 - WSZ) ? 0 : (p < (128 - SSH) ? 1 : 2);
}

// 64x192 = (64x192 smem) @ (192x192 global, staged via smem) into per-thread acc[4][12].
// Thread layout: rg = tid>>4 (rows 4rg..4rg+3), cg = tid&15 (cols {4cg, 4cg+64, 4cg+128}+0..3).
__device__ __forceinline__ void gemm192(const float* __restrict__ sIn,
                                        const float* __restrict__ Wg,
                                        float* __restrict__ sStage,
                                        int rg, int cg, int tid,
                                        float acc[4][12])
{
#pragma unroll
    for (int r = 0; r < 4; r++)
#pragma unroll
        for (int j = 0; j < 12; j++) acc[r][j] = 0.f;

    for (int kb = 0; kb < CC; kb += 16) {
        __syncthreads();                      // previous stage fully consumed
        {
            const float4* wsrc = (const float4*)(Wg + (size_t)kb * CC);
            float4* wdst = (float4*)sStage;
            for (int i = tid; i < 768; i += 256) wdst[i] = wsrc[i];  // 16x192 floats
        }
        __syncthreads();
#pragma unroll
        for (int kk = 0; kk < 16; kk++) {
            float a0 = sIn[(4 * rg + 0) * CC + kb + kk];
            float a1 = sIn[(4 * rg + 1) * CC + kb + kk];
            float a2 = sIn[(4 * rg + 2) * CC + kb + kk];
            float a3 = sIn[(4 * rg + 3) * CC + kb + kk];
#pragma unroll
            for (int jj = 0; jj < 3; jj++) {
                float4 w4 = *(const float4*)&sStage[kk * CC + 4 * cg + 64 * jj];
                acc[0][jj*4+0] = fmaf(a0, w4.x, acc[0][jj*4+0]);
                acc[0][jj*4+1] = fmaf(a0, w4.y, acc[0][jj*4+1]);
                acc[0][jj*4+2] = fmaf(a0, w4.z, acc[0][jj*4+2]);
                acc[0][jj*4+3] = fmaf(a0, w4.w, acc[0][jj*4+3]);
                acc[1][jj*4+0] = fmaf(a1, w4.x, acc[1][jj*4+0]);
                acc[1][jj*4+1] = fmaf(a1, w4.y, acc[1][jj*4+1]);
                acc[1][jj*4+2] = fmaf(a1, w4.z, acc[1][jj*4+2]);
                acc[1][jj*4+3] = fmaf(a1, w4.w, acc[1][jj*4+3]);
                acc[2][jj*4+0] = fmaf(a2, w4.x, acc[2][jj*4+0]);
                acc[2][jj*4+1] = fmaf(a2, w4.y, acc[2][jj*4+1]);
                acc[2][jj*4+2] = fmaf(a2, w4.z, acc[2][jj*4+2]);
                acc[2][jj*4+3] = fmaf(a2, w4.w, acc[2][jj*4+3]);
                acc[3][jj*4+0] = fmaf(a3, w4.x, acc[3][jj*4+0]);
                acc[3][jj*4+1] = fmaf(a3, w4.y, acc[3][jj*4+1]);
                acc[3][jj*4+2] = fmaf(a3, w4.z, acc[3][jj*4+2]);
                acc[3][jj*4+3] = fmaf(a3, w4.w, acc[3][jj*4+3]);
            }
        }
    }
}

// ---------------------------------------------------------------------------
// Kernel 1: windowed attention + residual + LN1 -> g_x1
// grid = 2048 (b * 256 + window), block = 256
// ---------------------------------------------------------------------------
__global__ __launch_bounds__(256) void attn_kernel(
    const float* __restrict__ x,
    const float* __restrict__ wq, const float* __restrict__ bq,
    const float* __restrict__ wk, const float* __restrict__ bk,
    const float* __restrict__ wv, const float* __restrict__ bv,
    const float* __restrict__ wp, const float* __restrict__ bp,
    const float* __restrict__ rpbt,
    const float* __restrict__ g1, const float* __restrict__ beta1)
{
    extern __shared__ float sm[];
    float* sXW  = sm;                    // 64*192  (input window; later per-head output o)
    float* sQ   = sXW + NTOK * CC;       // 64*192  (later pre-LN rows)
    float* sKT  = sQ  + NTOK * CC;       // 192*65  (K transposed, padded)
    float* sV   = sKT + CC * KT_LD;      // 64*192
    float* sA   = sV  + NTOK * CC;       // 64*64   (weight stage / attn scores)
    float* sRPB = sA  + NTOK * NTOK;     // 225*6

    const int tid = threadIdx.x;
    const int b  = blockIdx.x >> 8;
    const int wi = blockIdx.x & 255;
    const int wr = wi >> 4, wc = wi & 15;

    // ---- load shifted window tile: token t=(i,j) <- x[b, (wr*8+i+4)%128, (wc*8+j+4)%128, :]
    {
        int row = tid >> 2, part = tid & 3;
        int i = row >> 3, j = row & 7;
        int oh = (wr * WSZ + i + SSH) & 127;
        int ow = (wc * WSZ + j + SSH) & 127;
        const float4* src = (const float4*)(x + ((size_t)b * LL + oh * 128 + ow) * CC);
        float4* dst = (float4*)(sXW + row * CC);
#pragma unroll
        for (int p = part; p < 48; p += 4) dst[p] = src[p];
    }
    for (int i = tid; i < 225 * NHEAD; i += 256) sRPB[i] = rpbt[i];
    // (visibility guaranteed by first __syncthreads inside gemm192)

    const int rg = tid >> 4, cg = tid & 15;
    float acc[4][12];
    const float qscale = 0.17677669529663689f;   // 32^-0.5

    // ---- Q = (xw @ wq + bq) * scale
    gemm192(sXW, wq, sA, rg, cg, tid, acc);
#pragma unroll
    for (int r = 0; r < 4; r++)
#pragma unroll
    for (int jj = 0; jj < 3; jj++) {
        int col = 4 * cg + 64 * jj;
        float4 v;
        v.x = (acc[r][jj*4+0] + bq[col+0]) * qscale;
        v.y = (acc[r][jj*4+1] + bq[col+1]) * qscale;
        v.z = (acc[r][jj*4+2] + bq[col+2]) * qscale;
        v.w = (acc[r][jj*4+3] + bq[col+3]) * qscale;
        *(float4*)&sQ[(4 * rg + r) * CC + col] = v;
    }

    // ---- K = xw @ wk + bk, stored transposed: sKT[col][token]
    gemm192(sXW, wk, sA, rg, cg, tid, acc);
#pragma unroll
    for (int jj = 0; jj < 3; jj++)
#pragma unroll
    for (int c = 0; c < 4; c++) {
        int col = 4 * cg + 64 * jj + c;
        float bias = bk[col];
#pragma unroll
        for (int r = 0; r < 4; r++)
            sKT[col * KT_LD + 4 * rg + r] = acc[r][jj*4+c] + bias;
    }

    // ---- V = xw @ wv + bv
    gemm192(sXW, wv, sA, rg, cg, tid, acc);
#pragma unroll
    for (int r = 0; r < 4; r++)
#pragma unroll
    for (int jj = 0; jj < 3; jj++) {
        int col = 4 * cg + 64 * jj;
        float4 v;
        v.x = acc[r][jj*4+0] + bv[col+0];
        v.y = acc[r][jj*4+1] + bv[col+1];
        v.z = acc[r][jj*4+2] + bv[col+2];
        v.w = acc[r][jj*4+3] + bv[col+3];
        *(float4*)&sV[(4 * rg + r) * CC + col] = v;
    }

    // ---- attention per head (o written into sXW, overwriting consumed input)
    for (int h = 0; h < NHEAD; h++) {
        __syncthreads();   // sQ/sKT/sV visible; sA free (prev AV reads / V-gemm done)
        const int hoff = h * HD;

        // scores: thread tile 4a x 4b
        float s[4][4];
#pragma unroll
        for (int r = 0; r < 4; r++)
#pragma unroll
            for (int c = 0; c < 4; c++) s[r][c] = 0.f;
        for (int d = 0; d < HD; d++) {
            float q0 = sQ[(4 * rg + 0) * CC + hoff + d];
            float q1 = sQ[(4 * rg + 1) * CC + hoff + d];
            float q2 = sQ[(4 * rg + 2) * CC + hoff + d];
            float q3 = sQ[(4 * rg + 3) * CC + hoff + d];
            float k0 = sKT[(hoff + d) * KT_LD + 4 * cg + 0];
            float k1 = sKT[(hoff + d) * KT_LD + 4 * cg + 1];
            float k2 = sKT[(hoff + d) * KT_LD + 4 * cg + 2];
            float k3 = sKT[(hoff + d) * KT_LD + 4 * cg + 3];
            s[0][0]=fmaf(q0,k0,s[0][0]); s[0][1]=fmaf(q0,k1,s[0][1]); s[0][2]=fmaf(q0,k2,s[0][2]); s[0][3]=fmaf(q0,k3,s[0][3]);
            s[1][0]=fmaf(q1,k0,s[1][0]); s[1][1]=fmaf(q1,k1,s[1][1]); s[1][2]=fmaf(q1,k2,s[1][2]); s[1][3]=fmaf(q1,k3,s[1][3]);
            s[2][0]=fmaf(q2,k0,s[2][0]); s[2][1]=fmaf(q2,k1,s[2][1]); s[2][2]=fmaf(q2,k2,s[2][2]); s[2][3]=fmaf(q2,k3,s[2][3]);
            s[3][0]=fmaf(q3,k0,s[3][0]); s[3][1]=fmaf(q3,k1,s[3][1]); s[3][2]=fmaf(q3,k2,s[3][2]); s[3][3]=fmaf(q3,k3,s[3][3]);
        }
        // + relative position bias + shifted-window mask, store to sA
#pragma unroll
        for (int r = 0; r < 4; r++) {
            int a = 4 * rg + r;
            int ia = a >> 3, ja = a & 7;
            int la = region_label(wr * WSZ + ia) * 3 + region_label(wc * WSZ + ja);
#pragma unroll
            for (int c = 0; c < 4; c++) {
                int bbk = 4 * cg + c;
                int ib = bbk >> 3, jb = bbk & 7;
                int lb = region_label(wr * WSZ + ib) * 3 + region_label(wc * WSZ + jb);
                int idx = (ia - ib + 7) * 15 + (ja - jb + 7);
                float msk = (la == lb) ? 0.f : -100.f;
                sA[a * NTOK + bbk] = s[r][c] + sRPB[idx * NHEAD + h] + msk;
            }
        }
        __syncthreads();

        // softmax: 4 threads per row
        {
            int a = tid >> 2, q4 = tid & 3;
            float* row = &sA[a * NTOK + q4 * 16];
            float mx = -1e30f;
#pragma unroll
            for (int j = 0; j < 16; j++) mx = fmaxf(mx, row[j]);
            mx = fmaxf(mx, __shfl_xor_sync(0xffffffffu, mx, 1));
            mx = fmaxf(mx, __shfl_xor_sync(0xffffffffu, mx, 2));
            float e[16]; float ssum = 0.f;
#pragma unroll
            for (int j = 0; j < 16; j++) { e[j] = expf(row[j] - mx); ssum += e[j]; }
            ssum += __shfl_xor_sync(0xffffffffu, ssum, 1);
            ssum += __shfl_xor_sync(0xffffffffu, ssum, 2);
            float inv = 1.f / ssum;
#pragma unroll
            for (int j = 0; j < 16; j++) row[j] = e[j] * inv;
        }
        __syncthreads();

        // o_h = attn @ V_h : thread tile 4a x 2d
        {
            int d0 = hoff + 2 * cg;
            float o[4][2];
#pragma unroll
            for (int r = 0; r < 4; r++) { o[r][0] = 0.f; o[r][1] = 0.f; }
            for (int t2 = 0; t2 < NTOK; t2++) {
                float p0 = sA[(4 * rg + 0) * NTOK + t2];
                float p1 = sA[(4 * rg + 1) * NTOK + t2];
                float p2 = sA[(4 * rg + 2) * NTOK + t2];
                float p3 = sA[(4 * rg + 3) * NTOK + t2];
                float v0 = sV[t2 * CC + d0];
                float v1 = sV[t2 * CC + d0 + 1];
                o[0][0]=fmaf(p0,v0,o[0][0]); o[0][1]=fmaf(p0,v1,o[0][1]);
                o[1][0]=fmaf(p1,v0,o[1][0]); o[1][1]=fmaf(p1,v1,o[1][1]);
                o[2][0]=fmaf(p2,v0,o[2][0]); o[2][1]=fmaf(p2,v1,o[2][1]);
                o[3][0]=fmaf(p3,v0,o[3][0]); o[3][1]=fmaf(p3,v1,o[3][1]);
            }
#pragma unroll
            for (int r = 0; r < 4; r++) {
                sXW[(4 * rg + r) * CC + d0]     = o[r][0];
                sXW[(4 * rg + r) * CC + d0 + 1] = o[r][1];
            }
        }
    }

    // ---- output projection + residual, pre-LN rows into sQ (reuse)
    gemm192(sXW, wp, sA, rg, cg, tid, acc);
#pragma unroll
    for (int r = 0; r < 4; r++) {
        int a = 4 * rg + r;
        int i = a >> 3, j = a & 7;
        int oh = (wr * WSZ + i + SSH) & 127;
        int ow = (wc * WSZ + j + SSH) & 127;
        const float* xr = x + ((size_t)b * LL + oh * 128 + ow) * CC;
#pragma unroll
        for (int jj = 0; jj < 3; jj++) {
            int col = 4 * cg + 64 * jj;
            float4 xs = *(const float4*)&xr[col];
            float4 v;
            v.x = acc[r][jj*4+0] + bp[col+0] + xs.x;
            v.y = acc[r][jj*4+1] + bp[col+1] + xs.y;
            v.z = acc[r][jj*4+2] + bp[col+2] + xs.z;
            v.w = acc[r][jj*4+3] + bp[col+3] + xs.w;
            *(float4*)&sQ[a * CC + col] = v;
        }
    }
    __syncthreads();

    // ---- LN1 and scatter x1 to (unshifted) global positions
    {
        int a = tid >> 2, q4 = tid & 3;
        const float* row = &sQ[a * CC];
        float s = 0.f;
#pragma unroll
        for (int j = 0; j < 48; j++) s += row[q4 * 48 + j];
        s += __shfl_xor_sync(0xffffffffu, s, 1);
        s += __shfl_xor_sync(0xffffffffu, s, 2);
        float mean = s * (1.f / CC);
        float vs = 0.f;
#pragma unroll
        for (int j = 0; j < 48; j++) { float d = row[q4 * 48 + j] - mean; vs = fmaf(d, d, vs); }
        vs += __shfl_xor_sync(0xffffffffu, vs, 1);
        vs += __shfl_xor_sync(0xffffffffu, vs, 2);
        float rstd = rsqrtf(vs * (1.f / CC) + EPS_LN);

        int i = a >> 3, j2 = a & 7;
        int oh = (wr * WSZ + i + SSH) & 127;
        int ow = (wc * WSZ + j2 + SSH) & 127;
        float* dst = g_x1 + ((size_t)b * LL + oh * 128 + ow) * CC;
#pragma unroll
        for (int j = 0; j < 48; j++) {
            int c = q4 * 48 + j;
            dst[c] = (row[c] - mean) * rstd * g1[c] + beta1[c];
        }
    }
}

// ---------------------------------------------------------------------------
// Kernel 2: fused MLP + residual + LN2 -> out
// grid = 131072/64 = 2048 blocks of 64 token rows, block = 256
// ---------------------------------------------------------------------------
__global__ __launch_bounds__(256) void mlp_kernel(
    const float* __restrict__ w1, const float* __restrict__ b1,
    const float* __restrict__ w2, const float* __restrict__ b2,
    const float* __restrict__ g2, const float* __restrict__ beta2,
    float* __restrict__ out)
{
    extern __shared__ float sm[];
    float* sX1 = sm;                 // 64*192
    float* sH  = sX1 + 64 * CC;      // 64*64  (gelu panel)
    float* sO  = sH  + 64 * 64;      // 64*192 (pre-LN rows)

    const int tid = threadIdx.x;
    const size_t rbase = (size_t)blockIdx.x * 64;

    {
        const float4* src = (const float4*)(g_x1 + rbase * CC);
        float4* dst = (float4*)sX1;
        for (int i = tid; i < 3072; i += 256) dst[i] = src[i];
    }
    __syncthreads();

    const int rg = tid >> 4, cg = tid & 15;
    float acc[4][12];
#pragma unroll
    for (int r = 0; r < 4; r++)
#pragma unroll
        for (int j = 0; j < 12; j++) acc[r][j] = 0.f;

    for (int f0 = 0; f0 < DFF; f0 += 64) {
        // GEMM1 panel: h[64 x 64] = x1 @ w1[:, f0:f0+64], thread tile 4 rows x 4 f-cols
        float h4[4][4];
#pragma unroll
        for (int r = 0; r < 4; r++)
#pragma unroll
            for (int c = 0; c < 4; c++) h4[r][c] = 0.f;
        for (int k = 0; k < CC; k++) {
            float a0 = sX1[(4 * rg + 0) * CC + k];
            float a1 = sX1[(4 * rg + 1) * CC + k];
            float a2 = sX1[(4 * rg + 2) * CC + k];
            float a3 = sX1[(4 * rg + 3) * CC + k];
            float4 w4 = *(const float4*)&w1[(size_t)k * DFF + f0 + 4 * cg];
            h4[0][0]=fmaf(a0,w4.x,h4[0][0]); h4[0][1]=fmaf(a0,w4.y,h4[0][1]); h4[0][2]=fmaf(a0,w4.z,h4[0][2]); h4[0][3]=fmaf(a0,w4.w,h4[0][3]);
            h4[1][0]=fmaf(a1,w4.x,h4[1][0]); h4[1][1]=fmaf(a1,w4.y,h4[1][1]); h4[1][2]=fmaf(a1,w4.z,h4[1][2]); h4[1][3]=fmaf(a1,w4.w,h4[1][3]);
            h4[2][0]=fmaf(a2,w4.x,h4[2][0]); h4[2][1]=fmaf(a2,w4.y,h4[2][1]); h4[2][2]=fmaf(a2,w4.z,h4[2][2]); h4[2][3]=fmaf(a2,w4.w,h4[2][3]);
            h4[3][0]=fmaf(a3,w4.x,h4[3][0]); h4[3][1]=fmaf(a3,w4.y,h4[3][1]); h4[3][2]=fmaf(a3,w4.z,h4[3][2]); h4[3][3]=fmaf(a3,w4.w,h4[3][3]);
        }
        // bias + exact gelu
        {
            float4 bb = *(const float4*)&b1[f0 + 4 * cg];
            float bv[4] = {bb.x, bb.y, bb.z, bb.w};
#pragma unroll
            for (int r = 0; r < 4; r++)
#pragma unroll
            for (int c = 0; c < 4; c++) {
                float hv = h4[r][c] + bv[c];
                h4[r][c] = 0.5f * hv * (1.0f + erff(hv * 0.70710678118654752f));
            }
        }
        __syncthreads();   // previous panel fully consumed by GEMM2
#pragma unroll
        for (int r = 0; r < 4; r++) {
            float4 v = make_float4(h4[r][0], h4[r][1], h4[r][2], h4[r][3]);
            *(float4*)&sH[(4 * rg + r) * 64 + 4 * cg] = v;
        }
        __syncthreads();
        // GEMM2 accumulate: acc += h_panel @ w2[f0:f0+64, :]
        for (int ff = 0; ff < 64; ff++) {
            float p0 = sH[(4 * rg + 0) * 64 + ff];
            float p1 = sH[(4 * rg + 1) * 64 + ff];
            float p2 = sH[(4 * rg + 2) * 64 + ff];
            float p3 = sH[(4 * rg + 3) * 64 + ff];
#pragma unroll
            for (int jj = 0; jj < 3; jj++) {
                float4 w4 = *(const float4*)&w2[(size_t)(f0 + ff) * CC + 4 * cg + 64 * jj];
                acc[0][jj*4+0]=fmaf(p0,w4.x,acc[0][jj*4+0]); acc[0][jj*4+1]=fmaf(p0,w4.y,acc[0][jj*4+1]);
                acc[0][jj*4+2]=fmaf(p0,w4.z,acc[0][jj*4+2]); acc[0][jj*4+3]=fmaf(p0,w4.w,acc[0][jj*4+3]);
                acc[1][jj*4+0]=fmaf(p1,w4.x,acc[1][jj*4+0]); acc[1][jj*4+1]=fmaf(p1,w4.y,acc[1][jj*4+1]);
                acc[1][jj*4+2]=fmaf(p1,w4.z,acc[1][jj*4+2]); acc[1][jj*4+3]=fmaf(p1,w4.w,acc[1][jj*4+3]);
                acc[2][jj*4+0]=fmaf(p2,w4.x,acc[2][jj*4+0]); acc[2][jj*4+1]=fmaf(p2,w4.y,acc[2][jj*4+1]);
                acc[2][jj*4+2]=fmaf(p2,w4.z,acc[2][jj*4+2]); acc[2][jj*4+3]=fmaf(p2,w4.w,acc[2][jj*4+3]);
                acc[3][jj*4+0]=fmaf(p3,w4.x,acc[3][jj*4+0]); acc[3][jj*4+1]=fmaf(p3,w4.y,acc[3][jj*4+1]);
                acc[3][jj*4+2]=fmaf(p3,w4.z,acc[3][jj*4+2]); acc[3][jj*4+3]=fmaf(p3,w4.w,acc[3][jj*4+3]);
            }
        }
    }

    // residual + bias, pre-LN rows
#pragma unroll
    for (int r = 0; r < 4; r++)
#pragma unroll
    for (int jj = 0; jj < 3; jj++) {
        int col = 4 * cg + 64 * jj;
        int a = 4 * rg + r;
        float4 xs = *(const float4*)&sX1[a * CC + col];
        float4 v;
        v.x = acc[r][jj*4+0] + b2[col+0] + xs.x;
        v.y = acc[r][jj*4+1] + b2[col+1] + xs.y;
        v.z = acc[r][jj*4+2] + b2[col+2] + xs.z;
        v.w = acc[r][jj*4+3] + b2[col+3] + xs.w;
        *(float4*)&sO[a * CC + col] = v;
    }
    __syncthreads();

    // LN2 -> out (rows contiguous)
    {
        int a = tid >> 2, q4 = tid & 3;
        const float* row = &sO[a * CC];
        float s = 0.f;
#pragma unroll
        for (int j = 0; j < 48; j++) s += row[q4 * 48 + j];
        s += __shfl_xor_sync(0xffffffffu, s, 1);
        s += __shfl_xor_sync(0xffffffffu, s, 2);
        float mean = s * (1.f / CC);
        float vs = 0.f;
#pragma unroll
        for (int j = 0; j < 48; j++) { float d = row[q4 * 48 + j] - mean; vs = fmaf(d, d, vs); }
        vs += __shfl_xor_sync(0xffffffffu, vs, 1);
        vs += __shfl_xor_sync(0xffffffffu, vs, 2);
        float rstd = rsqrtf(vs * (1.f / CC) + EPS_LN);
        float* dst = out + (rbase + a) * CC;
#pragma unroll
        for (int j = 0; j < 48; j++) {
            int c = q4 * 48 + j;
            dst[c] = (row[c] - mean) * rstd * g2[c] + beta2[c];
        }
    }
}

// ---------------------------------------------------------------------------

#define SMEM_ATTN ((NTOK*CC*3 + CC*KT_LD + NTOK*NTOK + 225*NHEAD) * (int)sizeof(float))
#define SMEM_MLP  ((64*CC + 64*64 + 64*CC) * (int)sizeof(float))

extern "C" void kernel_launch(void* const* d_in, const int* in_sizes, int n_in,
                              void* d_out, int out_size)
{
    const float* x     = (const float*)d_in[0];
    const float* wq    = (const float*)d_in[1];
    const float* bq    = (const float*)d_in[2];
    const float* wk    = (const float*)d_in[3];
    const float* bk    = (const float*)d_in[4];
    const float* wv    = (const float*)d_in[5];
    const float* bv    = (const float*)d_in[6];
    const float* wp    = (const float*)d_in[7];
    const float* bp    = (const float*)d_in[8];
    const float* rpbt  = (const float*)d_in[9];
    const float* g1    = (const float*)d_in[10];
    const float* beta1 = (const float*)d_in[11];
    const float* g2    = (const float*)d_in[12];
    const float* beta2 = (const float*)d_in[13];
    const float* w1m   = (const float*)d_in[14];
    const float* b1m   = (const float*)d_in[15];
    const float* w2m   = (const float*)d_in[16];
    const float* b2m   = (const float*)d_in[17];
    (void)in_sizes; (void)n_in; (void)out_size;

    (void)cudaFuncSetAttribute(attn_kernel, cudaFuncAttributeMaxDynamicSharedMemorySize, SMEM_ATTN);
    (void)cudaFuncSetAttribute(mlp_kernel,  cudaFuncAttributeMaxDynamicSharedMemorySize, SMEM_MLP);

    attn_kernel<<<BB * 256, 256, SMEM_ATTN>>>(x, wq, bq, wk, bk, wv, bv, wp, bp,
                                              rpbt, g1, beta1);
    mlp_kernel<<<(BB * LL) / 64, 256, SMEM_MLP>>>(w1m, b1m, w2m, b2m, g2, beta2,
                                                  (float*)d_out);
}

// round 3
// speedup vs baseline: 1.0486x; 1.0486x over previous
#include <cuda_runtime.h>
#include <cstdint>

// Swin Transformer block, fp32 + packed f32x2 FMA (Blackwell FFMA2).
// B=8, H=W=128, C=192, NH=6, hd=32, WS=8 (N=64 tokens/window), shift=4, DFF=768.

#define CC     192
#define LL     16384
#define BB     8
#define NHEAD  6
#define HD     32
#define WSZ    8
#define NTOK   64
#define SSH    4
#define DFF    768
#define EPS_LN 1e-7f
#define KT_LD  68          // padded row stride for transposed K (16B-aligned ull2 loads)

typedef unsigned long long ull;

// scratch: x1 = LN1(shortcut + attn_out)
__device__ float g_x1[(size_t)BB * LL * CC];

// ---------------- f32x2 helpers ----------------
__device__ __forceinline__ ull f2bcast(float x) {
    ull r; asm("mov.b64 %0, {%1, %1};" : "=l"(r) : "f"(x)); return r;
}
__device__ __forceinline__ ull ffma2(ull a, ull b, ull c) {
    ull d; asm("fma.rn.f32x2 %0, %1, %2, %3;" : "=l"(d) : "l"(a), "l"(b), "l"(c)); return d;
}
__device__ __forceinline__ float2 f2unpk(ull v) {
    float2 f; asm("mov.b64 {%0, %1}, %2;" : "=f"(f.x), "=f"(f.y) : "l"(v)); return f;
}

__device__ __forceinline__ int region_label(int p) {
    return p < (128 - WSZ) ? 0 : (p < (128 - SSH) ? 1 : 2);
}

// 64x192 = (64x192 smem) @ (192x192 global, staged via smem), f32x2 col-packed.
// rg = tid>>4 (rows 4rg..4rg+3), cg = tid&15; col pairs p: col = 4cg + 64*(p>>1) + 2*(p&1).
__device__ __forceinline__ void gemm192(const float* __restrict__ sIn,
                                        const float* __restrict__ Wg,
                                        float* __restrict__ sStage,
                                        int rg, int cg, int tid,
                                        ull acc2[4][6])
{
#pragma unroll
    for (int r = 0; r < 4; r++)
#pragma unroll
        for (int p = 0; p < 6; p++) acc2[r][p] = 0ULL;

    for (int kb = 0; kb < CC; kb += 16) {
        __syncthreads();                      // previous stage fully consumed
        {
            const float4* wsrc = (const float4*)(Wg + (size_t)kb * CC);
            float4* wdst = (float4*)sStage;
            for (int i = tid; i < 768; i += 256) wdst[i] = wsrc[i];  // 16x192 floats
        }
        __syncthreads();
#pragma unroll
        for (int kk = 0; kk < 16; kk++) {
            ull a0 = f2bcast(sIn[(4 * rg + 0) * CC + kb + kk]);
            ull a1 = f2bcast(sIn[(4 * rg + 1) * CC + kb + kk]);
            ull a2 = f2bcast(sIn[(4 * rg + 2) * CC + kb + kk]);
            ull a3 = f2bcast(sIn[(4 * rg + 3) * CC + kb + kk]);
#pragma unroll
            for (int jj = 0; jj < 3; jj++) {
                ulonglong2 w = *(const ulonglong2*)&sStage[kk * CC + 4 * cg + 64 * jj];
                acc2[0][2*jj+0] = ffma2(a0, w.x, acc2[0][2*jj+0]);
                acc2[0][2*jj+1] = ffma2(a0, w.y, acc2[0][2*jj+1]);
                acc2[1][2*jj+0] = ffma2(a1, w.x, acc2[1][2*jj+0]);
                acc2[1][2*jj+1] = ffma2(a1, w.y, acc2[1][2*jj+1]);
                acc2[2][2*jj+0] = ffma2(a2, w.x, acc2[2][2*jj+0]);
                acc2[2][2*jj+1] = ffma2(a2, w.y, acc2[2][2*jj+1]);
                acc2[3][2*jj+0] = ffma2(a3, w.x, acc2[3][2*jj+0]);
                acc2[3][2*jj+1] = ffma2(a3, w.y, acc2[3][2*jj+1]);
            }
        }
    }
}

// ---------------------------------------------------------------------------
// Kernel 1: windowed attention + residual + LN1 -> g_x1
// ---------------------------------------------------------------------------
__global__ __launch_bounds__(256) void attn_kernel(
    const float* __restrict__ x,
    const float* __restrict__ wq, const float* __restrict__ bq,
    const float* __restrict__ wk, const float* __restrict__ bk,
    const float* __restrict__ wv, const float* __restrict__ bv,
    const float* __restrict__ wp, const float* __restrict__ bp,
    const float* __restrict__ rpbt,
    const float* __restrict__ g1, const float* __restrict__ beta1)
{
    extern __shared__ float sm[];
    float* sXW  = sm;                    // 64*192  (input window; later per-head output o)
    float* sQ   = sXW + NTOK * CC;       // 64*192  (later pre-LN rows)
    float* sKT  = sQ  + NTOK * CC;       // 192*68  (K transposed, padded)
    float* sV   = sKT + CC * KT_LD;      // 64*192
    float* sA   = sV  + NTOK * CC;       // 64*64   (weight stage / attn scores)
    float* sRPB = sA  + NTOK * NTOK;     // 225*6

    const int tid = threadIdx.x;
    const int b  = blockIdx.x >> 8;
    const int wi = blockIdx.x & 255;
    const int wr = wi >> 4, wc = wi & 15;

    // ---- load shifted window tile
    {
        int row = tid >> 2, part = tid & 3;
        int i = row >> 3, j = row & 7;
        int oh = (wr * WSZ + i + SSH) & 127;
        int ow = (wc * WSZ + j + SSH) & 127;
        const float4* src = (const float4*)(x + ((size_t)b * LL + oh * 128 + ow) * CC);
        float4* dst = (float4*)(sXW + row * CC);
#pragma unroll
        for (int p = part; p < 48; p += 4) dst[p] = src[p];
    }
    for (int i = tid; i < 225 * NHEAD; i += 256) sRPB[i] = rpbt[i];

    const int rg = tid >> 4, cg = tid & 15;
    ull acc2[4][6];
    const float qscale = 0.17677669529663689f;   // 32^-0.5

    // ---- Q = (xw @ wq + bq) * scale
    gemm192(sXW, wq, sA, rg, cg, tid, acc2);
#pragma unroll
    for (int p = 0; p < 6; p++) {
        int col = 4 * cg + 64 * (p >> 1) + 2 * (p & 1);
        float b0 = bq[col], b1v = bq[col + 1];
#pragma unroll
        for (int r = 0; r < 4; r++) {
            float2 t = f2unpk(acc2[r][p]);
            t.x = (t.x + b0) * qscale;
            t.y = (t.y + b1v) * qscale;
            *(float2*)&sQ[(4 * rg + r) * CC + col] = t;
        }
    }

    // ---- K = xw @ wk + bk, stored transposed
    gemm192(sXW, wk, sA, rg, cg, tid, acc2);
#pragma unroll
    for (int p = 0; p < 6; p++) {
        int col = 4 * cg + 64 * (p >> 1) + 2 * (p & 1);
        float b0 = bk[col], b1v = bk[col + 1];
#pragma unroll
        for (int r = 0; r < 4; r++) {
            float2 t = f2unpk(acc2[r][p]);
            sKT[(col    ) * KT_LD + 4 * rg + r] = t.x + b0;
            sKT[(col + 1) * KT_LD + 4 * rg + r] = t.y + b1v;
        }
    }

    // ---- V = xw @ wv + bv
    gemm192(sXW, wv, sA, rg, cg, tid, acc2);
#pragma unroll
    for (int p = 0; p < 6; p++) {
        int col = 4 * cg + 64 * (p >> 1) + 2 * (p & 1);
        float b0 = bv[col], b1v = bv[col + 1];
#pragma unroll
        for (int r = 0; r < 4; r++) {
            float2 t = f2unpk(acc2[r][p]);
            t.x += b0; t.y += b1v;
            *(float2*)&sV[(4 * rg + r) * CC + col] = t;
        }
    }

    // ---- attention per head
    for (int h = 0; h < NHEAD; h++) {
        __syncthreads();   // sQ/sKT/sV visible; sA free
        const int hoff = h * HD;

        // scores: 4a x 4b tile, b-pairs packed
        ull s2[4][2];
#pragma unroll
        for (int r = 0; r < 4; r++) { s2[r][0] = 0ULL; s2[r][1] = 0ULL; }
#pragma unroll 4
        for (int d = 0; d < HD; d++) {
            ull q0 = f2bcast(sQ[(4 * rg + 0) * CC + hoff + d]);
            ull q1 = f2bcast(sQ[(4 * rg + 1) * CC + hoff + d]);
            ull q2 = f2bcast(sQ[(4 * rg + 2) * CC + hoff + d]);
            ull q3 = f2bcast(sQ[(4 * rg + 3) * CC + hoff + d]);
            ulonglong2 kv = *(const ulonglong2*)&sKT[(hoff + d) * KT_LD + 4 * cg];
            s2[0][0] = ffma2(q0, kv.x, s2[0][0]); s2[0][1] = ffma2(q0, kv.y, s2[0][1]);
            s2[1][0] = ffma2(q1, kv.x, s2[1][0]); s2[1][1] = ffma2(q1, kv.y, s2[1][1]);
            s2[2][0] = ffma2(q2, kv.x, s2[2][0]); s2[2][1] = ffma2(q2, kv.y, s2[2][1]);
            s2[3][0] = ffma2(q3, kv.x, s2[3][0]); s2[3][1] = ffma2(q3, kv.y, s2[3][1]);
        }
        // + rpb + shifted-window mask, store to sA
#pragma unroll
        for (int r = 0; r < 4; r++) {
            int a = 4 * rg + r;
            int ia = a >> 3, ja = a & 7;
            int la = region_label(wr * WSZ + ia) * 3 + region_label(wc * WSZ + ja);
#pragma unroll
            for (int half = 0; half < 2; half++) {
                float2 t = f2unpk(s2[r][half]);
#pragma unroll
                for (int c2 = 0; c2 < 2; c2++) {
                    int bbk = 4 * cg + 2 * half + c2;
                    int ib = bbk >> 3, jb = bbk & 7;
                    int lb = region_label(wr * WSZ + ib) * 3 + region_label(wc * WSZ + jb);
                    int idx = (ia - ib + 7) * 15 + (ja - jb + 7);
                    float msk = (la == lb) ? 0.f : -100.f;
                    float sv = (c2 ? t.y : t.x);
                    sA[a * NTOK + bbk] = sv + sRPB[idx * NHEAD + h] + msk;
                }
            }
        }
        __syncthreads();

        // softmax: 4 threads per row
        {
            int a = tid >> 2, q4 = tid & 3;
            float* row = &sA[a * NTOK + q4 * 16];
            float mx = -1e30f;
#pragma unroll
            for (int j = 0; j < 16; j++) mx = fmaxf(mx, row[j]);
            mx = fmaxf(mx, __shfl_xor_sync(0xffffffffu, mx, 1));
            mx = fmaxf(mx, __shfl_xor_sync(0xffffffffu, mx, 2));
            float e[16]; float ssum = 0.f;
#pragma unroll
            for (int j = 0; j < 16; j++) { e[j] = expf(row[j] - mx); ssum += e[j]; }
            ssum += __shfl_xor_sync(0xffffffffu, ssum, 1);
            ssum += __shfl_xor_sync(0xffffffffu, ssum, 2);
            float inv = 1.f / ssum;
#pragma unroll
            for (int j = 0; j < 16; j++) row[j] = e[j] * inv;
        }
        __syncthreads();

        // o_h = attn @ V_h : 4a rows x d-pair
        {
            int d0 = hoff + 2 * cg;
            ull o2[4];
#pragma unroll
            for (int r = 0; r < 4; r++) o2[r] = 0ULL;
#pragma unroll 4
            for (int t2 = 0; t2 < NTOK; t2++) {
                ull p0 = f2bcast(sA[(4 * rg + 0) * NTOK + t2]);
                ull p1 = f2bcast(sA[(4 * rg + 1) * NTOK + t2]);
                ull p2 = f2bcast(sA[(4 * rg + 2) * NTOK + t2]);
                ull p3 = f2bcast(sA[(4 * rg + 3) * NTOK + t2]);
                ull vv = *(const ull*)&sV[t2 * CC + d0];
                o2[0] = ffma2(p0, vv, o2[0]);
                o2[1] = ffma2(p1, vv, o2[1]);
                o2[2] = ffma2(p2, vv, o2[2]);
                o2[3] = ffma2(p3, vv, o2[3]);
            }
#pragma unroll
            for (int r = 0; r < 4; r++) {
                float2 t = f2unpk(o2[r]);
                *(float2*)&sXW[(4 * rg + r) * CC + d0] = t;
            }
        }
    }

    // ---- output projection + residual, pre-LN rows into sQ
    gemm192(sXW, wp, sA, rg, cg, tid, acc2);
#pragma unroll
    for (int r = 0; r < 4; r++) {
        int a = 4 * rg + r;
        int i = a >> 3, j = a & 7;
        int oh = (wr * WSZ + i + SSH) & 127;
        int ow = (wc * WSZ + j + SSH) & 127;
        const float* xr = x + ((size_t)b * LL + oh * 128 + ow) * CC;
#pragma unroll
        for (int p = 0; p < 6; p++) {
            int col = 4 * cg + 64 * (p >> 1) + 2 * (p & 1);
            float2 xs = *(const float2*)&xr[col];
            float2 t = f2unpk(acc2[r][p]);
            t.x += bp[col]     + xs.x;
            t.y += bp[col + 1] + xs.y;
            *(float2*)&sQ[a * CC + col] = t;
        }
    }
    __syncthreads();

    // ---- LN1 and scatter x1 to (unshifted) global positions
    {
        int a = tid >> 2, q4 = tid & 3;
        const float* row = &sQ[a * CC];
        float s = 0.f;
#pragma unroll
        for (int j = 0; j < 48; j++) s += row[q4 * 48 + j];
        s += __shfl_xor_sync(0xffffffffu, s, 1);
        s += __shfl_xor_sync(0xffffffffu, s, 2);
        float mean = s * (1.f / CC);
        float vs = 0.f;
#pragma unroll
        for (int j = 0; j < 48; j++) { float d = row[q4 * 48 + j] - mean; vs = fmaf(d, d, vs); }
        vs += __shfl_xor_sync(0xffffffffu, vs, 1);
        vs += __shfl_xor_sync(0xffffffffu, vs, 2);
        float rstd = rsqrtf(vs * (1.f / CC) + EPS_LN);

        int i = a >> 3, j2 = a & 7;
        int oh = (wr * WSZ + i + SSH) & 127;
        int ow = (wc * WSZ + j2 + SSH) & 127;
        float* dst = g_x1 + ((size_t)b * LL + oh * 128 + ow) * CC;
#pragma unroll
        for (int j = 0; j < 48; j++) {
            int c = q4 * 48 + j;
            dst[c] = (row[c] - mean) * rstd * g1[c] + beta1[c];
        }
    }
}

// ---------------------------------------------------------------------------
// Kernel 2: fused MLP + residual + LN2 -> out  (f32x2, smem-staged w2, shfl-LN)
// grid = 2048 blocks of 64 token rows, block = 256
// ---------------------------------------------------------------------------
__global__ __launch_bounds__(256) void mlp_kernel(
    const float* __restrict__ w1, const float* __restrict__ b1,
    const float* __restrict__ w2, const float* __restrict__ b2,
    const float* __restrict__ g2, const float* __restrict__ beta2,
    float* __restrict__ out)
{
    extern __shared__ float sm[];
    float* sX1 = sm;                 // 64*192
    float* sH  = sX1 + 64 * CC;      // 64*64   (gelu panel)
    float* sW2 = sH  + 64 * 64;      // 64*192  (w2 panel stage)

    const int tid = threadIdx.x;
    const size_t rbase = (size_t)blockIdx.x * 64;

    {
        const float4* src = (const float4*)(g_x1 + rbase * CC);
        float4* dst = (float4*)sX1;
        for (int i = tid; i < 3072; i += 256) dst[i] = src[i];
    }

    const int rg = tid >> 4, cg = tid & 15;
    const uint32_t sW2_u32 = (uint32_t)__cvta_generic_to_shared(sW2);

    ull acc2[4][6];
#pragma unroll
    for (int r = 0; r < 4; r++)
#pragma unroll
        for (int p = 0; p < 6; p++) acc2[r][p] = 0ULL;

    for (int f0 = 0; f0 < DFF; f0 += 64) {
        __syncthreads();   // prev GEMM2 done reading sW2/sH; sX1 visible on first iter

        // async stage of w2 panel (contiguous 12288 floats): hidden behind GEMM1
        {
            const float* src = w2 + (size_t)f0 * CC;
#pragma unroll
            for (int rep = 0; rep < 12; rep++) {
                int i = rep * 256 + tid;
                uint32_t d = sW2_u32 + (uint32_t)i * 16u;
                const float* s = src + i * 4;
                asm volatile("cp.async.cg.shared.global [%0], [%1], 16;"
                             :: "r"(d), "l"(s) : "memory");
            }
            asm volatile("cp.async.commit_group;" ::: "memory");
        }

        // GEMM1 panel: h[64x64] = x1 @ w1[:, f0:f0+64]  (w1 read direct from global)
        ull h2[4][2];
#pragma unroll
        for (int r = 0; r < 4; r++) { h2[r][0] = 0ULL; h2[r][1] = 0ULL; }
#pragma unroll 4
        for (int k = 0; k < CC; k++) {
            ull a0 = f2bcast(sX1[(4 * rg + 0) * CC + k]);
            ull a1 = f2bcast(sX1[(4 * rg + 1) * CC + k]);
            ull a2 = f2bcast(sX1[(4 * rg + 2) * CC + k]);
            ull a3 = f2bcast(sX1[(4 * rg + 3) * CC + k]);
            ulonglong2 w = *(const ulonglong2*)&w1[(size_t)k * DFF + f0 + 4 * cg];
            h2[0][0] = ffma2(a0, w.x, h2[0][0]); h2[0][1] = ffma2(a0, w.y, h2[0][1]);
            h2[1][0] = ffma2(a1, w.x, h2[1][0]); h2[1][1] = ffma2(a1, w.y, h2[1][1]);
            h2[2][0] = ffma2(a2, w.x, h2[2][0]); h2[2][1] = ffma2(a2, w.y, h2[2][1]);
            h2[3][0] = ffma2(a3, w.x, h2[3][0]); h2[3][1] = ffma2(a3, w.y, h2[3][1]);
        }
        // bias + exact gelu -> sH
        {
            float4 bb = *(const float4*)&b1[f0 + 4 * cg];
#pragma unroll
            for (int r = 0; r < 4; r++) {
                float2 t0 = f2unpk(h2[r][0]);
                float2 t1 = f2unpk(h2[r][1]);
                float h0 = t0.x + bb.x, h1 = t0.y + bb.y;
                float h2v = t1.x + bb.z, h3 = t1.y + bb.w;
                float2 g0, gg1;
                g0.x  = 0.5f * h0  * (1.0f + erff(h0  * 0.70710678118654752f));
                g0.y  = 0.5f * h1  * (1.0f + erff(h1  * 0.70710678118654752f));
                gg1.x = 0.5f * h2v * (1.0f + erff(h2v * 0.70710678118654752f));
                gg1.y = 0.5f * h3  * (1.0f + erff(h3  * 0.70710678118654752f));
                *(float2*)&sH[(4 * rg + r) * 64 + 4 * cg]     = g0;
                *(float2*)&sH[(4 * rg + r) * 64 + 4 * cg + 2] = gg1;
            }
        }
        asm volatile("cp.async.wait_group 0;" ::: "memory");
        __syncthreads();   // sH + sW2 panel ready

        // GEMM2 accumulate: acc += gelu_panel @ w2_panel (both smem)
#pragma unroll 4
        for (int ff = 0; ff < 64; ff++) {
            ull p0 = f2bcast(sH[(4 * rg + 0) * 64 + ff]);
            ull p1 = f2bcast(sH[(4 * rg + 1) * 64 + ff]);
            ull p2 = f2bcast(sH[(4 * rg + 2) * 64 + ff]);
            ull p3 = f2bcast(sH[(4 * rg + 3) * 64 + ff]);
#pragma unroll
            for (int jj = 0; jj < 3; jj++) {
                ulonglong2 w = *(const ulonglong2*)&sW2[ff * CC + 4 * cg + 64 * jj];
                acc2[0][2*jj+0] = ffma2(p0, w.x, acc2[0][2*jj+0]);
                acc2[0][2*jj+1] = ffma2(p0, w.y, acc2[0][2*jj+1]);
                acc2[1][2*jj+0] = ffma2(p1, w.x, acc2[1][2*jj+0]);
                acc2[1][2*jj+1] = ffma2(p1, w.y, acc2[1][2*jj+1]);
                acc2[2][2*jj+0] = ffma2(p2, w.x, acc2[2][2*jj+0]);
                acc2[2][2*jj+1] = ffma2(p2, w.y, acc2[2][2*jj+1]);
                acc2[3][2*jj+0] = ffma2(p3, w.x, acc2[3][2*jj+0]);
                acc2[3][2*jj+1] = ffma2(p3, w.y, acc2[3][2*jj+1]);
            }
        }
    }

    // ---- bias + residual + LN2 (shuffle over the 16 cg lanes) -> out
    float v[4][12];
#pragma unroll
    for (int r = 0; r < 4; r++) {
        int row = 4 * rg + r;
#pragma unroll
        for (int p = 0; p < 6; p++) {
            int col = 4 * cg + 64 * (p >> 1) + 2 * (p & 1);
            float2 t = f2unpk(acc2[r][p]);
            float2 xs = *(const float2*)&sX1[row * CC + col];
            v[r][2*p+0] = t.x + b2[col]     + xs.x;
            v[r][2*p+1] = t.y + b2[col + 1] + xs.y;
        }
    }
#pragma unroll
    for (int r = 0; r < 4; r++) {
        float s = 0.f;
#pragma unroll
        for (int j = 0; j < 12; j++) s += v[r][j];
        s += __shfl_xor_sync(0xffffffffu, s, 1);
        s += __shfl_xor_sync(0xffffffffu, s, 2);
        s += __shfl_xor_sync(0xffffffffu, s, 4);
        s += __shfl_xor_sync(0xffffffffu, s, 8);
        float mean = s * (1.f / CC);
        float q = 0.f;
#pragma unroll
        for (int j = 0; j < 12; j++) { float d = v[r][j] - mean; q = fmaf(d, d, q); }
        q += __shfl_xor_sync(0xffffffffu, q, 1);
        q += __shfl_xor_sync(0xffffffffu, q, 2);
        q += __shfl_xor_sync(0xffffffffu, q, 4);
        q += __shfl_xor_sync(0xffffffffu, q, 8);
        float rstd = rsqrtf(q * (1.f / CC) + EPS_LN);
        float* dst = out + (rbase + 4 * rg + r) * CC;
#pragma unroll
        for (int p = 0; p < 6; p++) {
            int col = 4 * cg + 64 * (p >> 1) + 2 * (p & 1);
            float2 o;
            o.x = (v[r][2*p+0] - mean) * rstd * g2[col]     + beta2[col];
            o.y = (v[r][2*p+1] - mean) * rstd * g2[col + 1] + beta2[col + 1];
            *(float2*)&dst[col] = o;
        }
    }
}

// ---------------------------------------------------------------------------

#define SMEM_ATTN ((NTOK*CC*3 + CC*KT_LD + NTOK*NTOK + 225*NHEAD) * (int)sizeof(float))
#define SMEM_MLP  ((64*CC + 64*64 + 64*CC) * (int)sizeof(float))

extern "C" void kernel_launch(void* const* d_in, const int* in_sizes, int n_in,
                              void* d_out, int out_size)
{
    const float* x     = (const float*)d_in[0];
    const float* wq    = (const float*)d_in[1];
    const float* bq    = (const float*)d_in[2];
    const float* wk    = (const float*)d_in[3];
    const float* bk    = (const float*)d_in[4];
    const float* wv    = (const float*)d_in[5];
    const float* bv    = (const float*)d_in[6];
    const float* wp    = (const float*)d_in[7];
    const float* bp    = (const float*)d_in[8];
    const float* rpbt  = (const float*)d_in[9];
    const float* g1    = (const float*)d_in[10];
    const float* beta1 = (const float*)d_in[11];
    const float* g2    = (const float*)d_in[12];
    const float* beta2 = (const float*)d_in[13];
    const float* w1m   = (const float*)d_in[14];
    const float* b1m   = (const float*)d_in[15];
    const float* w2m   = (const float*)d_in[16];
    const float* b2m   = (const float*)d_in[17];
    (void)in_sizes; (void)n_in; (void)out_size;

    (void)cudaFuncSetAttribute(attn_kernel, cudaFuncAttributeMaxDynamicSharedMemorySize, SMEM_ATTN);
    (void)cudaFuncSetAttribute(mlp_kernel,  cudaFuncAttributeMaxDynamicSharedMemorySize, SMEM_MLP);

    attn_kernel<<<BB * 256, 256, SMEM_ATTN>>>(x, wq, bq, wk, bk, wv, bv, wp, bp,
                                              rpbt, g1, beta1);
    mlp_kernel<<<(BB * LL) / 64, 256, SMEM_MLP>>>(w1m, b1m, w2m, b2m, g2, beta2,
                                                  (float*)d_out);
}